// round 3
// baseline (speedup 1.0000x reference)
#include <cuda_runtime.h>
#include <math.h>

#define N_SRC   16384
#define N_DST   8192
#define NODE_IN 128
#define EDGE_IN 64
#define TIME_D  128
#define D_MODEL 320
#define NH      8
#define DK      64
#define HID     128

// ---------------- scratch (device globals; no allocations) ----------------
__device__ float g_proj[(long)N_SRC * 1536];   // [0:512) node_k | [512:1024) node_v | [1024:1536) qh
__device__ float g_packW[128 * 1536];
__device__ float g_biasq[512];
__device__ float g_cosph[128];
__device__ float g_fcwT[512 * 320];
__device__ float g_nodewT[448 * 128];
__device__ float g_wvT[8 * 192 * 64];
__device__ float g_wfold[(long)N_DST * 1536];
__device__ float g_et[(long)N_DST * 1536];
__device__ float g_ctx[(long)N_DST * 512];
__device__ float g_x[(long)N_DST * 320];
__device__ float g_hcat[(long)N_DST * 448];

// ---------------- f32x2 packed-FMA helpers ----------------
__device__ __forceinline__ unsigned long long pack2(float x, float y) {
    unsigned long long r;
    asm("mov.b64 %0, {%1, %2};" : "=l"(r) : "f"(x), "f"(y));
    return r;
}
__device__ __forceinline__ void unpack2(unsigned long long v, float& x, float& y) {
    asm("mov.b64 {%0, %1}, %2;" : "=f"(x), "=f"(y) : "l"(v));
}
__device__ __forceinline__ void ffma2(unsigned long long& d, unsigned long long a, unsigned long long b) {
    asm("fma.rn.f32x2 %0, %1, %2, %0;" : "+l"(d) : "l"(a), "l"(b));
}

// ---------------- prep / pack kernel ----------------
__global__ void prep_kernel(const float* __restrict__ wks, const float* __restrict__ wvs,
                            const float* __restrict__ wqs, const float* __restrict__ fcw,
                            const float* __restrict__ nw,  const float* __restrict__ ph)
{
    const int P0 = 196608;
    const int P1 = P0 + 163840;
    const int P2 = P1 + 57344;
    const int P3 = P2 + 98304;
    const int P4 = P3 + 512;
    const int P5 = P4 + 128;
    int t = blockIdx.x * blockDim.x + threadIdx.x;
    if (t < P0) {
        int d = t / 1536, r = t % 1536;
        float v;
        if (r < 512)       v = wks[r * 320 + d];
        else if (r < 1024) v = wvs[(r - 512) * 320 + d];
        else               v = wqs[(r - 1024) * 320 + d];
        g_packW[t] = v;
    } else if (t < P1) {
        int i = t - P0; int j = i / 320, c = i % 320;
        g_fcwT[i] = fcw[c * 512 + j];
    } else if (t < P2) {
        int i = t - P1; int c = i / 128, o = i % 128;
        g_nodewT[i] = nw[o * 448 + c];
    } else if (t < P3) {
        int i = t - P2; int h = i / 12288; int rem = i % 12288;
        int c = rem / 64, d = rem % 64;
        g_wvT[i] = wvs[(h * 64 + d) * 320 + 128 + c];
    } else if (t < P4) {
        int j = t - P3;
        float acc = 0.f;
        for (int d = 0; d < 128; d++) acc += cosf(ph[d]) * wqs[j * 320 + 192 + d];
        g_biasq[j] = acc;
    } else if (t < P5) {
        int d = t - P4;
        g_cosph[d] = cosf(ph[d]);
    }
}

// ---------------- register-tiled SGEMM, f32x2 FMA, duplicated-A smem ----------------
// TM must be 8, TN 8. EPI: 0 store, 1 accumulate, 3 relu(v+bias), 4 qh-bias, 5 fc epilogue
template<int BM, int BN, int BK, int TM, int TN, int EPI>
__global__ void gemm_k(const float* __restrict__ A, const float* __restrict__ B,
                       float* __restrict__ C,
                       int M, int N, int Kd, int lda, int ldb, int ldc,
                       long bsA, long bsB, long bsC,
                       const float* __restrict__ bias,
                       const float* __restrict__ aux1,
                       const float* __restrict__ aux2)
{
    constexpr int THREADS = (BM / TM) * (BN / TN);
    __shared__ __align__(16) float2 sA[BK][BM + 2];   // duplicated value (v,v)
    __shared__ __align__(16) float  sB[BK][BN + 4];
    const int bz = blockIdx.z;
    A += (long)bz * bsA; B += (long)bz * bsB; C += (long)bz * bsC;
    const int tm0 = blockIdx.y * BM;
    const int tn0 = blockIdx.x * BN;
    const int tid = threadIdx.x;
    const int tcol = tid % (BN / TN);
    const int trow = tid / (BN / TN);

    unsigned long long acc2[TM][TN / 2];
#pragma unroll
    for (int i = 0; i < TM; i++)
#pragma unroll
        for (int j = 0; j < TN / 2; j++) acc2[i][j] = 0ull;

    for (int k0 = 0; k0 < Kd; k0 += BK) {
        constexpr int AITER = (BM * BK / 4 + THREADS - 1) / THREADS;
#pragma unroll
        for (int it = 0; it < AITER; it++) {
            int idx = tid + it * THREADS;
            if (idx < BM * BK / 4) {
                int m = idx >> 2, q = idx & 3;
                float4 v = *(const float4*)&A[(long)(tm0 + m) * lda + k0 + q * 4];
                sA[q * 4 + 0][m] = make_float2(v.x, v.x);
                sA[q * 4 + 1][m] = make_float2(v.y, v.y);
                sA[q * 4 + 2][m] = make_float2(v.z, v.z);
                sA[q * 4 + 3][m] = make_float2(v.w, v.w);
            }
        }
        constexpr int BITER = (BK * BN / 4 + THREADS - 1) / THREADS;
#pragma unroll
        for (int it = 0; it < BITER; it++) {
            int idx = tid + it * THREADS;
            if (idx < BK * BN / 4) {
                int kk = idx / (BN / 4), n4 = idx % (BN / 4);
                float4 v = *(const float4*)&B[(long)(k0 + kk) * ldb + tn0 + n4 * 4];
                *(float4*)&sB[kk][n4 * 4] = v;
            }
        }
        __syncthreads();
#pragma unroll
        for (int kk = 0; kk < BK; kk++) {
            const unsigned long long* ap = (const unsigned long long*)&sA[kk][trow * TM];
            unsigned long long b2[TN / 2];
            {
                float4 bx = *(const float4*)&sB[kk][tcol * TN];
                b2[0] = pack2(bx.x, bx.y);
                b2[1] = pack2(bx.z, bx.w);
                if (TN == 8) {
                    float4 by = *(const float4*)&sB[kk][tcol * TN + 4];
                    b2[2] = pack2(by.x, by.y);
                    b2[3] = pack2(by.z, by.w);
                }
            }
#pragma unroll
            for (int i = 0; i < TM; i++) {
                unsigned long long a2 = ap[i];
#pragma unroll
                for (int j = 0; j < TN / 2; j++) ffma2(acc2[i][j], a2, b2[j]);
            }
        }
        __syncthreads();
    }

#pragma unroll
    for (int i = 0; i < TM; i++) {
        int row = tm0 + trow * TM + i;
#pragma unroll
        for (int j2 = 0; j2 < TN / 2; j2++) {
            float v0, v1;
            unpack2(acc2[i][j2], v0, v1);
#pragma unroll
            for (int s = 0; s < 2; s++) {
                float v = s ? v1 : v0;
                int col = tn0 + tcol * TN + j2 * 2 + s;
                long off = (long)row * ldc + col;
                if (EPI == 1) v += C[off];
                if (EPI == 3) v = fmaxf(v + bias[col], 0.f);
                if (EPI == 4) { if (col >= 1024) v += aux1[col - 1024]; }
                if (EPI == 5) {
                    v += bias[col];
                    if (col < 128)        v += aux1[(long)row * 128 + col];
                    else if (col >= 192)  v += aux2[col - 192];
                }
                C[off] = v;
            }
        }
    }
}

// ---------------- fused attention kernel: one block per dst node ----------------
__global__ void attn_kernel(const float* __restrict__ ef, const float* __restrict__ dt,
                            const int* __restrict__ nidx,
                            const float* __restrict__ freq, const float* __restrict__ ph)
{
    const int n = blockIdx.x;
    const int tid = threadIdx.x;
    __shared__ __align__(16) float s_qh[512];
    __shared__ __align__(16) float s_wf[1536];
    __shared__ __align__(16) float s_te[32][132];   // conflict-free for float4
    __shared__ __align__(16) float s_e[32][68];
    __shared__ float s_dt[32];
    __shared__ int   s_idx[16];                     // 16 distinct neighbors
    __shared__ float s_fr[128], s_ph[128];
    __shared__ float s_at[8][33];
    __shared__ float s_a2[8][17];                   // pair-summed attention
    __shared__ float s_ns[8][17];                   // node score per (h, neighbor)

    for (int i = tid; i < 512;  i += 256) s_qh[i] = g_proj[(long)n * 1536 + 1024 + i];
    for (int i = tid; i < 1536; i += 256) s_wf[i] = g_wfold[(long)n * 1536 + i];
    {
        const float4* ef4 = (const float4*)(ef + (long)n * 2048);
        for (int i = tid; i < 512; i += 256) {
            int l = i >> 4, c4 = i & 15;
            *(float4*)&s_e[l][c4 * 4] = ef4[i];
        }
    }
    if (tid < 128) { s_fr[tid] = freq[tid]; s_ph[tid] = ph[tid]; }
    if (tid < 32)  s_dt[tid] = dt[(long)n * 32 + tid];
    if (tid < 16)  s_idx[tid] = nidx[n * 16 + tid];
    __syncthreads();

    // temporal encoding (exact cosf)
    for (int i = tid; i < 4096; i += 256) {
        int l = i >> 7, d = i & 127;
        s_te[l][d] = cosf(s_dt[l] * s_fr[d] + s_ph[d]);
    }
    __syncthreads();

    const int h = tid >> 5, l = tid & 31;

    // node scores: warp h computes dot(qh_h, node_k[idx_j, h]) for 16 distinct j,
    // 8 lanes per j, 8 dims per lane (coalesced 256B reads per j).
    {
#pragma unroll
        for (int jb = 0; jb < 16; jb += 4) {
            int j = jb + (l >> 3);
            int d0 = (l & 7) * 8;
            const float4* p = (const float4*)(g_proj + (long)s_idx[j] * 1536 + h * 64 + d0);
            const float4* q = (const float4*)(s_qh + h * 64 + d0);
            float4 x0 = p[0], x1 = p[1];
            float4 q0 = q[0], q1 = q[1];
            float d = x0.x * q0.x + x0.y * q0.y + x0.z * q0.z + x0.w * q0.w
                    + x1.x * q1.x + x1.y * q1.y + x1.z * q1.z + x1.w * q1.w;
            d += __shfl_xor_sync(0xffffffffu, d, 1);
            d += __shfl_xor_sync(0xffffffffu, d, 2);
            d += __shfl_xor_sync(0xffffffffu, d, 4);
            if ((l & 7) == 0) s_ns[h][j] = d;
        }
        __syncwarp();
    }

    // scores (edge + te parts) + softmax: lane = l
    {
        float sc = s_ns[h][l >> 1];
        const float4* ev = (const float4*)(&s_e[l][0]);
        const float4* we = (const float4*)(s_wf + h * 192);
#pragma unroll
        for (int j = 0; j < 16; j++) {
            float4 a = ev[j], b = we[j];
            sc += a.x * b.x + a.y * b.y + a.z * b.z + a.w * b.w;
        }
        const float4* tv = (const float4*)(&s_te[l][0]);
        const float4* wt = (const float4*)(s_wf + h * 192 + 64);
#pragma unroll
        for (int j = 0; j < 32; j++) {
            float4 a = tv[j], b = wt[j];
            sc += a.x * b.x + a.y * b.y + a.z * b.z + a.w * b.w;
        }
        sc *= 0.125f; // 1/sqrt(64)
        float mx = sc;
        for (int o = 16; o; o >>= 1) mx = fmaxf(mx, __shfl_xor_sync(0xffffffffu, mx, o));
        float ex = expf(sc - mx);
        float sm = ex;
        for (int o = 16; o; o >>= 1) sm += __shfl_xor_sync(0xffffffffu, sm, o);
        float p = ex / sm;
        s_at[h][l] = p;
        float pp = p + __shfl_xor_sync(0xffffffffu, p, 1);
        if ((l & 1) == 0) s_a2[h][l >> 1] = pp;
    }
    __syncthreads();

    // ctx node part: pair-summed attention over 16 distinct node_v rows (coalesced over j)
    for (int j = tid; j < 512; j += 256) {
        int hh = j >> 6;
        float a0 = 0.f;
#pragma unroll 4
        for (int r = 0; r < 16; r++)
            a0 += s_a2[hh][r] * g_proj[(long)s_idx[r] * 1536 + 512 + j];
        g_ctx[(long)n * 512 + j] = a0;
    }
    // ebar / tbar
    for (int o = tid; o < 1536; o += 256) {
        int hh = o / 192, c = o % 192;
        float a0 = 0.f;
        if (c < 64) {
#pragma unroll
            for (int ll = 0; ll < 32; ll++) a0 += s_at[hh][ll] * s_e[ll][c];
        } else {
            int d = c - 64;
#pragma unroll
            for (int ll = 0; ll < 32; ll++) a0 += s_at[hh][ll] * s_te[ll][d];
        }
        g_et[(long)n * 1536 + o] = a0;
    }
}

// ---------------- layernorm + concat ----------------
__global__ void ln_kernel(const float* __restrict__ lng, const float* __restrict__ lnb,
                          const float* __restrict__ nf)
{
    const int n = blockIdx.x, tid = threadIdx.x; // 128 threads
    float xv[3];
    int cnt = 0;
    float s = 0.f, sq = 0.f;
    for (int i = tid; i < 320; i += 128) {
        float v = g_x[(long)n * 320 + i];
        xv[cnt++] = v;
        s += v; sq += v * v;
    }
    __shared__ float rs[4], rq[4];
    for (int o = 16; o; o >>= 1) {
        s  += __shfl_xor_sync(0xffffffffu, s,  o);
        sq += __shfl_xor_sync(0xffffffffu, sq, o);
    }
    int wid = tid >> 5, lane = tid & 31;
    if (lane == 0) { rs[wid] = s; rq[wid] = sq; }
    __syncthreads();
    float ts = rs[0] + rs[1] + rs[2] + rs[3];
    float tq = rq[0] + rq[1] + rq[2] + rq[3];
    float mu = ts * (1.f / 320.f);
    float var = tq * (1.f / 320.f) - mu * mu;
    float inv = rsqrtf(var + 1e-5f);
    cnt = 0;
    for (int i = tid; i < 320; i += 128)
        g_hcat[(long)n * 448 + 128 + i] = lng[i] * (xv[cnt++] - mu) * inv + lnb[i];
    g_hcat[(long)n * 448 + tid] = nf[(long)n * 128 + tid];
}

// ---------------- launch ----------------
extern "C" void kernel_launch(void* const* d_in, const int* in_sizes, int n_in,
                              void* d_out, int out_size) {
    const float* nf   = (const float*)d_in[0];
    const float* ef   = (const float*)d_in[1];
    const float* dt   = (const float*)d_in[2];
    const int*   nidx = (const int*)  d_in[3];
    const float* freq = (const float*)d_in[4];
    const float* ph   = (const float*)d_in[5];
    const float* wqs  = (const float*)d_in[6];
    const float* wks  = (const float*)d_in[7];
    const float* wvs  = (const float*)d_in[8];
    const float* fcw  = (const float*)d_in[9];
    const float* fcb  = (const float*)d_in[10];
    const float* lng  = (const float*)d_in[11];
    const float* lnb  = (const float*)d_in[12];
    const float* nw   = (const float*)d_in[13];
    const float* nb   = (const float*)d_in[14];
    float* out = (float*)d_out;

    float *p_proj, *p_packW, *p_biasq, *p_cosph, *p_fcwT, *p_nodewT, *p_wvT,
          *p_wfold, *p_et, *p_ctx, *p_x, *p_hcat;
    cudaGetSymbolAddress((void**)&p_proj,   g_proj);
    cudaGetSymbolAddress((void**)&p_packW,  g_packW);
    cudaGetSymbolAddress((void**)&p_biasq,  g_biasq);
    cudaGetSymbolAddress((void**)&p_cosph,  g_cosph);
    cudaGetSymbolAddress((void**)&p_fcwT,   g_fcwT);
    cudaGetSymbolAddress((void**)&p_nodewT, g_nodewT);
    cudaGetSymbolAddress((void**)&p_wvT,    g_wvT);
    cudaGetSymbolAddress((void**)&p_wfold,  g_wfold);
    cudaGetSymbolAddress((void**)&p_et,     g_et);
    cudaGetSymbolAddress((void**)&p_ctx,    g_ctx);
    cudaGetSymbolAddress((void**)&p_x,      g_x);
    cudaGetSymbolAddress((void**)&p_hcat,   g_hcat);

    // 1) pack weights / bias
    prep_kernel<<<(516736 + 255) / 256, 256>>>(wks, wvs, wqs, fcw, nw, ph);

    // 2) node_k | node_v | qh projection: (16384 x 1536) = nf(16384x128) @ packW(128x1536)
    gemm_k<128,128,16,8,8,4><<<dim3(12,128,1), 256>>>(
        nf, p_packW, p_proj, N_SRC, 1536, 128, 128, 1536, 1536,
        0, 0, 0, nullptr, p_biasq, nullptr);

    // 3) fold q into K-weights, per head: (8192x192) = qh_h(8192x64) @ Wk_h(64x192)
    gemm_k<128,64,16,8,8,0><<<dim3(3,64,8), 128>>>(
        p_proj + 1024, wks + 128, p_wfold, N_DST, 192, 64, 1536, 320, 1536,
        64, (long)64 * 320, 192, nullptr, nullptr, nullptr);

    // 4) fused attention per dst
    attn_kernel<<<N_DST, 256>>>(ef, dt, nidx, freq, ph);

    // 5) V projection (accumulate): per head (8192x64) += et_h(8192x192) @ WvT_h(192x64)
    gemm_k<128,64,16,8,8,1><<<dim3(1,64,8), 128>>>(
        p_et, p_wvT, p_ctx, N_DST, 64, 192, 1536, 64, 512,
        192, (long)192 * 64, 64, nullptr, nullptr, nullptr);

    // 6) fc: x = ctx @ fc_w^T + fc_b + q  (residual fused)
    gemm_k<128,64,16,8,8,5><<<dim3(5,64,1), 128>>>(
        p_ctx, p_fcwT, p_x, N_DST, 320, 512, 512, 320, 320,
        0, 0, 0, fcb, nf, p_cosph);

    // 7) layernorm + concat
    ln_kernel<<<N_DST, 128>>>(lng, lnb, nf);

    // 8) final: relu(hcat @ node_w^T + node_b)
    gemm_k<128,128,16,8,8,3><<<dim3(1,64,1), 256>>>(
        p_hcat, p_nodewT, out, N_DST, 128, 448, 448, 128, 128,
        0, 0, 0, nb, nullptr, nullptr);
}

// round 4
// speedup vs baseline: 1.3484x; 1.3484x over previous
#include <cuda_runtime.h>
#include <math.h>

#define N_SRC   16384
#define N_DST   8192
#define NODE_IN 128
#define EDGE_IN 64
#define TIME_D  128
#define D_MODEL 320
#define NH      8
#define DK      64
#define HID     128

// ---------------- scratch (device globals; no allocations) ----------------
__device__ float g_proj[(long)N_SRC * 1536];   // [0:512) node_k | [512:1024) node_v | [1024:1536) qh
__device__ float g_packW[128 * 1536];
__device__ float g_biasq[512];
__device__ float g_cosph[128];
__device__ float g_fcwT[512 * 320];
__device__ float g_nodewT[448 * 128];
__device__ float g_wvT[8 * 192 * 64];
__device__ float g_wfold[(long)N_DST * 1536];
__device__ float g_et[(long)N_DST * 1536];
__device__ float g_ctx[(long)N_DST * 512];
__device__ float g_x[(long)N_DST * 320];
__device__ float g_hcat[(long)N_DST * 448];

// ---------------- f32x2 packed-FMA helpers ----------------
__device__ __forceinline__ unsigned long long pack2(float x, float y) {
    unsigned long long r;
    asm("mov.b64 %0, {%1, %2};" : "=l"(r) : "f"(x), "f"(y));
    return r;
}
__device__ __forceinline__ void unpack2(unsigned long long v, float& x, float& y) {
    asm("mov.b64 {%0, %1}, %2;" : "=f"(x), "=f"(y) : "l"(v));
}
__device__ __forceinline__ void ffma2(unsigned long long& d, unsigned long long a, unsigned long long b) {
    asm("fma.rn.f32x2 %0, %1, %2, %0;" : "+l"(d) : "l"(a), "l"(b));
}

// ---------------- prep / pack kernel ----------------
__global__ void prep_kernel(const float* __restrict__ wks, const float* __restrict__ wvs,
                            const float* __restrict__ wqs, const float* __restrict__ fcw,
                            const float* __restrict__ nw,  const float* __restrict__ ph)
{
    const int P0 = 196608;
    const int P1 = P0 + 163840;
    const int P2 = P1 + 57344;
    const int P3 = P2 + 98304;
    const int P4 = P3 + 512;
    const int P5 = P4 + 128;
    int t = blockIdx.x * blockDim.x + threadIdx.x;
    if (t < P0) {
        int d = t / 1536, r = t % 1536;
        float v;
        if (r < 512)       v = wks[r * 320 + d];
        else if (r < 1024) v = wvs[(r - 512) * 320 + d];
        else               v = wqs[(r - 1024) * 320 + d];
        g_packW[t] = v;
    } else if (t < P1) {
        int i = t - P0; int j = i / 320, c = i % 320;
        g_fcwT[i] = fcw[c * 512 + j];
    } else if (t < P2) {
        int i = t - P1; int c = i / 128, o = i % 128;
        g_nodewT[i] = nw[o * 448 + c];
    } else if (t < P3) {
        int i = t - P2; int h = i / 12288; int rem = i % 12288;
        int c = rem / 64, d = rem % 64;
        g_wvT[i] = wvs[(h * 64 + d) * 320 + 128 + c];
    } else if (t < P4) {
        int j = t - P3;
        float acc = 0.f;
        for (int d = 0; d < 128; d++) acc += cosf(ph[d]) * wqs[j * 320 + 192 + d];
        g_biasq[j] = acc;
    } else if (t < P5) {
        int d = t - P4;
        g_cosph[d] = cosf(ph[d]);
    }
}

// ---------------- register-tiled SGEMM with packed f32x2 FMA (round-2 version) ----
// TM must be 8, TN in {4,8}. All dims tile multiples (true for all calls).
// EPI: 0 store, 1 accumulate, 3 relu(v+bias), 4 qh-bias (col>=1024), 5 fc epilogue
template<int BM, int BN, int BK, int TM, int TN, int EPI>
__global__ void gemm_k(const float* __restrict__ A, const float* __restrict__ B,
                       float* __restrict__ C,
                       int M, int N, int Kd, int lda, int ldb, int ldc,
                       long bsA, long bsB, long bsC,
                       const float* __restrict__ bias,
                       const float* __restrict__ aux1,
                       const float* __restrict__ aux2)
{
    constexpr int THREADS = (BM / TM) * (BN / TN);
    __shared__ __align__(16) float sA[BK][BM + 4];
    __shared__ __align__(16) float sB[BK][BN + 4];
    const int bz = blockIdx.z;
    A += (long)bz * bsA; B += (long)bz * bsB; C += (long)bz * bsC;
    const int tm0 = blockIdx.y * BM;
    const int tn0 = blockIdx.x * BN;
    const int tid = threadIdx.x;
    const int tcol = tid % (BN / TN);
    const int trow = tid / (BN / TN);

    unsigned long long acc2[TM][TN / 2];
#pragma unroll
    for (int i = 0; i < TM; i++)
#pragma unroll
        for (int j = 0; j < TN / 2; j++) acc2[i][j] = 0ull;

    for (int k0 = 0; k0 < Kd; k0 += BK) {
        constexpr int AITER = (BM * BK / 4 + THREADS - 1) / THREADS;
#pragma unroll
        for (int it = 0; it < AITER; it++) {
            int idx = tid + it * THREADS;
            if (idx < BM * BK / 4) {
                int m = idx >> 2, q = idx & 3;
                float4 v = *(const float4*)&A[(long)(tm0 + m) * lda + k0 + q * 4];
                sA[q * 4 + 0][m] = v.x;
                sA[q * 4 + 1][m] = v.y;
                sA[q * 4 + 2][m] = v.z;
                sA[q * 4 + 3][m] = v.w;
            }
        }
        constexpr int BITER = (BK * BN / 4 + THREADS - 1) / THREADS;
#pragma unroll
        for (int it = 0; it < BITER; it++) {
            int idx = tid + it * THREADS;
            if (idx < BK * BN / 4) {
                int kk = idx / (BN / 4), n4 = idx % (BN / 4);
                float4 v = *(const float4*)&B[(long)(k0 + kk) * ldb + tn0 + n4 * 4];
                *(float4*)&sB[kk][n4 * 4] = v;
            }
        }
        __syncthreads();
#pragma unroll
        for (int kk = 0; kk < BK; kk++) {
            float4 a0 = *(const float4*)&sA[kk][trow * TM];
            float4 a1 = *(const float4*)&sA[kk][trow * TM + 4];
            float av[8] = {a0.x, a0.y, a0.z, a0.w, a1.x, a1.y, a1.z, a1.w};
            unsigned long long b2[TN / 2];
            {
                float4 bx = *(const float4*)&sB[kk][tcol * TN];
                b2[0] = pack2(bx.x, bx.y);
                b2[1] = pack2(bx.z, bx.w);
                if (TN == 8) {
                    float4 by = *(const float4*)&sB[kk][tcol * TN + 4];
                    b2[2] = pack2(by.x, by.y);
                    b2[3] = pack2(by.z, by.w);
                }
            }
#pragma unroll
            for (int i = 0; i < TM; i++) {
                unsigned long long a2 = pack2(av[i], av[i]);
#pragma unroll
                for (int j = 0; j < TN / 2; j++) ffma2(acc2[i][j], a2, b2[j]);
            }
        }
        __syncthreads();
    }

#pragma unroll
    for (int i = 0; i < TM; i++) {
        int row = tm0 + trow * TM + i;
#pragma unroll
        for (int j2 = 0; j2 < TN / 2; j2++) {
            float v0, v1;
            unpack2(acc2[i][j2], v0, v1);
#pragma unroll
            for (int s = 0; s < 2; s++) {
                float v = s ? v1 : v0;
                int col = tn0 + tcol * TN + j2 * 2 + s;
                long off = (long)row * ldc + col;
                if (EPI == 1) v += C[off];
                if (EPI == 3) v = fmaxf(v + bias[col], 0.f);
                if (EPI == 4) { if (col >= 1024) v += aux1[col - 1024]; }
                if (EPI == 5) {
                    v += bias[col];
                    if (col < 128)        v += aux1[(long)row * 128 + col];
                    else if (col >= 192)  v += aux2[col - 192];
                }
                C[off] = v;
            }
        }
    }
}

// ---------------- fused attention kernel: one block per dst node ----------------
__global__ void attn_kernel(const float* __restrict__ ef, const float* __restrict__ dt,
                            const int* __restrict__ nidx,
                            const float* __restrict__ freq, const float* __restrict__ ph)
{
    const int n = blockIdx.x;
    const int tid = threadIdx.x;
    __shared__ __align__(16) float s_qh[512];
    __shared__ __align__(16) float s_wf[1536];
    __shared__ __align__(16) float s_te[32][132];   // conflict-free for float4
    __shared__ __align__(16) float s_e[32][68];
    __shared__ float s_dt[32];
    __shared__ int   s_idx[16];                     // 16 distinct neighbors
    __shared__ float s_fr[128], s_ph[128];
    __shared__ float s_at[8][33];
    __shared__ float s_a2[8][17];                   // pair-summed attention
    __shared__ float s_ns[8][17];                   // node score per (h, neighbor)

    for (int i = tid; i < 512;  i += 256) s_qh[i] = g_proj[(long)n * 1536 + 1024 + i];
    for (int i = tid; i < 1536; i += 256) s_wf[i] = g_wfold[(long)n * 1536 + i];
    {
        const float4* ef4 = (const float4*)(ef + (long)n * 2048);
        for (int i = tid; i < 512; i += 256) {
            int l = i >> 4, c4 = i & 15;
            *(float4*)&s_e[l][c4 * 4] = ef4[i];
        }
    }
    if (tid < 128) { s_fr[tid] = freq[tid]; s_ph[tid] = ph[tid]; }
    if (tid < 32)  s_dt[tid] = dt[(long)n * 32 + tid];
    if (tid < 16)  s_idx[tid] = nidx[n * 16 + tid];
    __syncthreads();

    // temporal encoding (exact cosf)
    for (int i = tid; i < 4096; i += 256) {
        int l = i >> 7, d = i & 127;
        s_te[l][d] = cosf(s_dt[l] * s_fr[d] + s_ph[d]);
    }
    __syncthreads();

    const int h = tid >> 5, l = tid & 31;

    // node scores: warp h computes dot(qh_h, node_k[idx_j, h]) for 16 distinct j,
    // 8 lanes per j, 8 dims per lane (coalesced 256B reads per j).
    {
#pragma unroll
        for (int jb = 0; jb < 16; jb += 4) {
            int j = jb + (l >> 3);
            int d0 = (l & 7) * 8;
            const float4* p = (const float4*)(g_proj + (long)s_idx[j] * 1536 + h * 64 + d0);
            const float4* q = (const float4*)(s_qh + h * 64 + d0);
            float4 x0 = p[0], x1 = p[1];
            float4 q0 = q[0], q1 = q[1];
            float d = x0.x * q0.x + x0.y * q0.y + x0.z * q0.z + x0.w * q0.w
                    + x1.x * q1.x + x1.y * q1.y + x1.z * q1.z + x1.w * q1.w;
            d += __shfl_xor_sync(0xffffffffu, d, 1);
            d += __shfl_xor_sync(0xffffffffu, d, 2);
            d += __shfl_xor_sync(0xffffffffu, d, 4);
            if ((l & 7) == 0) s_ns[h][j] = d;
        }
        __syncwarp();
    }

    // scores (edge + te parts) + softmax: lane = l
    {
        float sc = s_ns[h][l >> 1];
        const float4* ev = (const float4*)(&s_e[l][0]);
        const float4* we = (const float4*)(s_wf + h * 192);
#pragma unroll
        for (int j = 0; j < 16; j++) {
            float4 a = ev[j], b = we[j];
            sc += a.x * b.x + a.y * b.y + a.z * b.z + a.w * b.w;
        }
        const float4* tv = (const float4*)(&s_te[l][0]);
        const float4* wt = (const float4*)(s_wf + h * 192 + 64);
#pragma unroll
        for (int j = 0; j < 32; j++) {
            float4 a = tv[j], b = wt[j];
            sc += a.x * b.x + a.y * b.y + a.z * b.z + a.w * b.w;
        }
        sc *= 0.125f; // 1/sqrt(64)
        float mx = sc;
        for (int o = 16; o; o >>= 1) mx = fmaxf(mx, __shfl_xor_sync(0xffffffffu, mx, o));
        float ex = expf(sc - mx);
        float sm = ex;
        for (int o = 16; o; o >>= 1) sm += __shfl_xor_sync(0xffffffffu, sm, o);
        float p = ex / sm;
        s_at[h][l] = p;
        float pp = p + __shfl_xor_sync(0xffffffffu, p, 1);
        if ((l & 1) == 0) s_a2[h][l >> 1] = pp;
    }
    __syncthreads();

    // ctx node part: pair-summed attention over 16 distinct node_v rows,
    // float2-vectorized (each thread produces 2 consecutive outputs).
    {
        int j = tid * 2;                 // 256 threads * 2 = 512 outputs
        int hh = j >> 6;
        unsigned long long acc = 0ull;
#pragma unroll 4
        for (int r = 0; r < 16; r++) {
            float2 v = *(const float2*)&g_proj[(long)s_idx[r] * 1536 + 512 + j];
            float a = s_a2[hh][r];
            ffma2(acc, pack2(a, a), pack2(v.x, v.y));
        }
        float o0, o1;
        unpack2(acc, o0, o1);
        *(float2*)&g_ctx[(long)n * 512 + j] = make_float2(o0, o1);
    }
    // ebar / tbar, float2-vectorized: thread handles column pair (c2, c2+1)
    for (int p = tid; p < 768; p += 256) {
        int hh = p / 96, c2 = (p % 96) * 2;
        unsigned long long acc = 0ull;
        if (c2 < 64) {
#pragma unroll
            for (int ll = 0; ll < 32; ll++) {
                float2 e = *(const float2*)&s_e[ll][c2];
                float a = s_at[hh][ll];
                ffma2(acc, pack2(a, a), pack2(e.x, e.y));
            }
        } else {
            int d = c2 - 64;
#pragma unroll
            for (int ll = 0; ll < 32; ll++) {
                float2 t2 = *(const float2*)&s_te[ll][d];
                float a = s_at[hh][ll];
                ffma2(acc, pack2(a, a), pack2(t2.x, t2.y));
            }
        }
        float o0, o1;
        unpack2(acc, o0, o1);
        *(float2*)&g_et[(long)n * 1536 + hh * 192 + c2] = make_float2(o0, o1);
    }
}

// ---------------- layernorm + concat ----------------
__global__ void ln_kernel(const float* __restrict__ lng, const float* __restrict__ lnb,
                          const float* __restrict__ nf)
{
    const int n = blockIdx.x, tid = threadIdx.x; // 128 threads
    float xv[3];
    int cnt = 0;
    float s = 0.f, sq = 0.f;
    for (int i = tid; i < 320; i += 128) {
        float v = g_x[(long)n * 320 + i];
        xv[cnt++] = v;
        s += v; sq += v * v;
    }
    __shared__ float rs[4], rq[4];
    for (int o = 16; o; o >>= 1) {
        s  += __shfl_xor_sync(0xffffffffu, s,  o);
        sq += __shfl_xor_sync(0xffffffffu, sq, o);
    }
    int wid = tid >> 5, lane = tid & 31;
    if (lane == 0) { rs[wid] = s; rq[wid] = sq; }
    __syncthreads();
    float ts = rs[0] + rs[1] + rs[2] + rs[3];
    float tq = rq[0] + rq[1] + rq[2] + rq[3];
    float mu = ts * (1.f / 320.f);
    float var = tq * (1.f / 320.f) - mu * mu;
    float inv = rsqrtf(var + 1e-5f);
    cnt = 0;
    for (int i = tid; i < 320; i += 128)
        g_hcat[(long)n * 448 + 128 + i] = lng[i] * (xv[cnt++] - mu) * inv + lnb[i];
    g_hcat[(long)n * 448 + tid] = nf[(long)n * 128 + tid];
}

// ---------------- launch ----------------
extern "C" void kernel_launch(void* const* d_in, const int* in_sizes, int n_in,
                              void* d_out, int out_size) {
    const float* nf   = (const float*)d_in[0];
    const float* ef   = (const float*)d_in[1];
    const float* dt   = (const float*)d_in[2];
    const int*   nidx = (const int*)  d_in[3];
    const float* freq = (const float*)d_in[4];
    const float* ph   = (const float*)d_in[5];
    const float* wqs  = (const float*)d_in[6];
    const float* wks  = (const float*)d_in[7];
    const float* wvs  = (const float*)d_in[8];
    const float* fcw  = (const float*)d_in[9];
    const float* fcb  = (const float*)d_in[10];
    const float* lng  = (const float*)d_in[11];
    const float* lnb  = (const float*)d_in[12];
    const float* nw   = (const float*)d_in[13];
    const float* nb   = (const float*)d_in[14];
    float* out = (float*)d_out;

    float *p_proj, *p_packW, *p_biasq, *p_cosph, *p_fcwT, *p_nodewT, *p_wvT,
          *p_wfold, *p_et, *p_ctx, *p_x, *p_hcat;
    cudaGetSymbolAddress((void**)&p_proj,   g_proj);
    cudaGetSymbolAddress((void**)&p_packW,  g_packW);
    cudaGetSymbolAddress((void**)&p_biasq,  g_biasq);
    cudaGetSymbolAddress((void**)&p_cosph,  g_cosph);
    cudaGetSymbolAddress((void**)&p_fcwT,   g_fcwT);
    cudaGetSymbolAddress((void**)&p_nodewT, g_nodewT);
    cudaGetSymbolAddress((void**)&p_wvT,    g_wvT);
    cudaGetSymbolAddress((void**)&p_wfold,  g_wfold);
    cudaGetSymbolAddress((void**)&p_et,     g_et);
    cudaGetSymbolAddress((void**)&p_ctx,    g_ctx);
    cudaGetSymbolAddress((void**)&p_x,      g_x);
    cudaGetSymbolAddress((void**)&p_hcat,   g_hcat);

    // 1) pack weights / bias
    prep_kernel<<<(516736 + 255) / 256, 256>>>(wks, wvs, wqs, fcw, nw, ph);

    // 2) node_k | node_v | qh projection: (16384 x 1536) = nf(16384x128) @ packW(128x1536)
    gemm_k<128,128,16,8,8,4><<<dim3(12,128,1), 256>>>(
        nf, p_packW, p_proj, N_SRC, 1536, 128, 128, 1536, 1536,
        0, 0, 0, nullptr, p_biasq, nullptr);

    // 3) fold q into K-weights, per head: (8192x192) = qh_h(8192x64) @ Wk_h(64x192)
    gemm_k<128,64,16,8,4,0><<<dim3(3,64,8), 256>>>(
        p_proj + 1024, wks + 128, p_wfold, N_DST, 192, 64, 1536, 320, 1536,
        64, (long)64 * 320, 192, nullptr, nullptr, nullptr);

    // 4) fused attention per dst
    attn_kernel<<<N_DST, 256>>>(ef, dt, nidx, freq, ph);

    // 5) V projection (accumulate): per head (8192x64) += et_h(8192x192) @ WvT_h(192x64)
    gemm_k<128,64,16,8,4,1><<<dim3(1,64,8), 256>>>(
        p_et, p_wvT, p_ctx, N_DST, 64, 192, 1536, 64, 512,
        192, (long)192 * 64, 64, nullptr, nullptr, nullptr);

    // 6) fc: x = ctx @ fc_w^T + fc_b + q  (residual fused)
    gemm_k<128,64,16,8,4,5><<<dim3(5,64,1), 256>>>(
        p_ctx, p_fcwT, p_x, N_DST, 320, 512, 512, 320, 320,
        0, 0, 0, fcb, nf, p_cosph);

    // 7) layernorm + concat
    ln_kernel<<<N_DST, 128>>>(lng, lnb, nf);

    // 8) final: relu(hcat @ node_w^T + node_b)
    gemm_k<128,64,16,8,4,3><<<dim3(2,64,1), 256>>>(
        p_hcat, p_nodewT, out, N_DST, 128, 448, 448, 128, 128,
        0, 0, 0, nb, nullptr, nullptr);
}

// round 5
// speedup vs baseline: 1.5883x; 1.1780x over previous
#include <cuda_runtime.h>
#include <cuda_bf16.h>
#include <mma.h>
#include <math.h>

using namespace nvcuda;

#define N_SRC   16384
#define N_DST   8192
#define NODE_IN 128
#define EDGE_IN 64
#define TIME_D  128
#define D_MODEL 320
#define NH      8
#define DK      64
#define HID     128

// ---------------- scratch (device globals; no allocations) ----------------
__device__ float g_proj[(long)N_SRC * 1536];   // [0:512) node_k | [512:1024) node_v | [1024:1536) qh
__device__ float g_packW[128 * 1536];
__device__ float g_biasq[512];
__device__ float g_cosph[128];
__device__ float g_fcwT[512 * 320];            // (kept, unused by wmma path)
__device__ float g_nodewT[448 * 128];
__device__ float g_wvT[8 * 192 * 64];
__device__ float g_wfold[(long)N_DST * 1536];
__device__ float g_et[(long)N_DST * 1536];
__device__ float g_ctx[(long)N_DST * 512];
__device__ float g_x[(long)N_DST * 320];
__device__ float g_hcat[(long)N_DST * 448];
// bf16-split operands
__device__ __nv_bfloat16 g_A3[(long)N_SRC * 384];     // nf split [hi|lo|hi]
__device__ __nv_bfloat16 g_B3[(long)1536 * 384];      // packW^T split [hi|hi|lo]
__device__ __nv_bfloat16 g_ctx3[(long)N_DST * 1536];  // ctx split [hi|lo|hi]
__device__ __nv_bfloat16 g_fcw3[(long)320 * 1536];    // fc_w split [hi|hi|lo] (already N x K)

// ---------------- f32x2 packed-FMA helpers ----------------
__device__ __forceinline__ unsigned long long pack2(float x, float y) {
    unsigned long long r;
    asm("mov.b64 %0, {%1, %2};" : "=l"(r) : "f"(x), "f"(y));
    return r;
}
__device__ __forceinline__ void unpack2(unsigned long long v, float& x, float& y) {
    asm("mov.b64 {%0, %1}, %2;" : "=f"(x), "=f"(y) : "l"(v));
}
__device__ __forceinline__ void ffma2(unsigned long long& d, unsigned long long a, unsigned long long b) {
    asm("fma.rn.f32x2 %0, %1, %2, %0;" : "+l"(d) : "l"(a), "l"(b));
}

// ---------------- prep / pack kernel ----------------
__global__ void prep_kernel(const float* __restrict__ wks, const float* __restrict__ wvs,
                            const float* __restrict__ wqs, const float* __restrict__ fcw,
                            const float* __restrict__ nw,  const float* __restrict__ ph)
{
    const int P0 = 196608;
    const int P1 = P0 + 163840;
    const int P2 = P1 + 57344;
    const int P3 = P2 + 98304;
    const int P4 = P3 + 512;
    const int P5 = P4 + 128;
    int t = blockIdx.x * blockDim.x + threadIdx.x;
    if (t < P0) {
        int d = t / 1536, r = t % 1536;
        float v;
        if (r < 512)       v = wks[r * 320 + d];
        else if (r < 1024) v = wvs[(r - 512) * 320 + d];
        else               v = wqs[(r - 1024) * 320 + d];
        g_packW[t] = v;
    } else if (t < P1) {
        int i = t - P0; int j = i / 320, c = i % 320;
        g_fcwT[i] = fcw[c * 512 + j];
    } else if (t < P2) {
        int i = t - P1; int c = i / 128, o = i % 128;
        g_nodewT[i] = nw[o * 448 + c];
    } else if (t < P3) {
        int i = t - P2; int h = i / 12288; int rem = i % 12288;
        int c = rem / 64, d = rem % 64;
        g_wvT[i] = wvs[(h * 64 + d) * 320 + 128 + c];
    } else if (t < P4) {
        int j = t - P3;
        float acc = 0.f;
        for (int d = 0; d < 128; d++) acc += cosf(ph[d]) * wqs[j * 320 + 192 + d];
        g_biasq[j] = acc;
    } else if (t < P5) {
        int d = t - P4;
        g_cosph[d] = cosf(ph[d]);
    }
}

// ---------------- bf16-split conversion kernels ----------------
__global__ void convA_kernel(const float* __restrict__ nf) {  // 16384 x 128
    int i = blockIdx.x * 256 + threadIdx.x;
    if (i < N_SRC * 128) {
        int m = i >> 7, k = i & 127;
        float v = nf[i];
        __nv_bfloat16 hi = __float2bfloat16(v);
        __nv_bfloat16 lo = __float2bfloat16(v - __bfloat162float(hi));
        long b = (long)m * 384;
        g_A3[b + k] = hi;
        g_A3[b + 128 + k] = lo;
        g_A3[b + 256 + k] = hi;
    }
}
__global__ void convB_kernel() {  // packW (128 x 1536) -> B^T (1536 x 384)
    int i = blockIdx.x * 256 + threadIdx.x;
    if (i < 128 * 1536) {
        int k = i / 1536, n = i % 1536;
        float v = g_packW[i];
        __nv_bfloat16 hi = __float2bfloat16(v);
        __nv_bfloat16 lo = __float2bfloat16(v - __bfloat162float(hi));
        long b = (long)n * 384;
        g_B3[b + k] = hi;
        g_B3[b + 128 + k] = hi;
        g_B3[b + 256 + k] = lo;
    }
}
__global__ void convFc_kernel(const float* __restrict__ fcw) {  // fcw (320 x 512) -> (320 x 1536)
    int i = blockIdx.x * 256 + threadIdx.x;
    if (i < 320 * 512) {
        int c = i / 512, j = i % 512;
        float v = fcw[i];
        __nv_bfloat16 hi = __float2bfloat16(v);
        __nv_bfloat16 lo = __float2bfloat16(v - __bfloat162float(hi));
        long b = (long)c * 1536;
        g_fcw3[b + j] = hi;
        g_fcw3[b + 512 + j] = hi;
        g_fcw3[b + 1024 + j] = lo;
    }
}
__global__ void convCtx_kernel() {  // g_ctx (8192 x 512) -> (8192 x 1536)
    int i = blockIdx.x * 256 + threadIdx.x;
    if (i < N_DST * 512) {
        int n = i >> 9, j = i & 511;
        float v = g_ctx[i];
        __nv_bfloat16 hi = __float2bfloat16(v);
        __nv_bfloat16 lo = __float2bfloat16(v - __bfloat162float(hi));
        long b = (long)n * 1536;
        g_ctx3[b + j] = hi;
        g_ctx3[b + 512 + j] = lo;
        g_ctx3[b + 1024 + j] = hi;
    }
}
__global__ void qhbias_kernel() {  // add biasq to qh columns
    int i = blockIdx.x * 256 + threadIdx.x;
    if (i < N_DST * 512) {
        int n = i >> 9, j = i & 511;
        g_proj[(long)n * 1536 + 1024 + j] += g_biasq[j];
    }
}

// ---------------- bf16 wmma GEMM: C = A(MxK3) @ Bt(NxK3)^T, fp32 out ----------------
// 256 threads = 8 warps (4 x 2). BM=128; BN in {64,128}.
template<int BM, int BN>
__global__ void wmma_gemm(const __nv_bfloat16* __restrict__ A,
                          const __nv_bfloat16* __restrict__ Bt,
                          float* __restrict__ C,
                          int K3, int lda, int ldb, int ldc)
{
    constexpr int BK = 32;
    constexpr int PAD = 8;
    constexpr int FR_M = BM / 64;   // frags per warp in M (warps_m = 4)
    constexpr int FR_N = BN / 32;   // frags per warp in N (warps_n = 2)
    __shared__ __align__(16) __nv_bfloat16 sA[BM][BK + PAD];
    __shared__ __align__(16) __nv_bfloat16 sB[BN][BK + PAD];
    const int tid = threadIdx.x;
    const int wid = tid >> 5;
    const int wm = wid & 3;
    const int wn = wid >> 2;
    const int tm0 = blockIdx.y * BM;
    const int tn0 = blockIdx.x * BN;

    wmma::fragment<wmma::accumulator, 16, 16, 16, float> cf[FR_M][FR_N];
#pragma unroll
    for (int i = 0; i < FR_M; i++)
#pragma unroll
        for (int j = 0; j < FR_N; j++) wmma::fill_fragment(cf[i][j], 0.f);

    for (int k0 = 0; k0 < K3; k0 += BK) {
        constexpr int A_LD = BM * 4 / 256;   // int4 loads per thread
#pragma unroll
        for (int it = 0; it < A_LD; it++) {
            int idx = tid + it * 256;
            int r = idx >> 2, c8 = idx & 3;
            *(int4*)&sA[r][c8 * 8] = *(const int4*)&A[(long)(tm0 + r) * lda + k0 + c8 * 8];
        }
        constexpr int B_LD = BN * 4 / 256;
#pragma unroll
        for (int it = 0; it < B_LD; it++) {
            int idx = tid + it * 256;
            int r = idx >> 2, c8 = idx & 3;
            *(int4*)&sB[r][c8 * 8] = *(const int4*)&Bt[(long)(tn0 + r) * ldb + k0 + c8 * 8];
        }
        __syncthreads();
#pragma unroll
        for (int kk = 0; kk < BK; kk += 16) {
            wmma::fragment<wmma::matrix_a, 16, 16, 16, __nv_bfloat16, wmma::row_major> af[FR_M];
            wmma::fragment<wmma::matrix_b, 16, 16, 16, __nv_bfloat16, wmma::col_major> bf[FR_N];
#pragma unroll
            for (int i = 0; i < FR_M; i++)
                wmma::load_matrix_sync(af[i], &sA[wm * 32 + i * 16][kk], BK + PAD);
#pragma unroll
            for (int j = 0; j < FR_N; j++)
                wmma::load_matrix_sync(bf[j], &sB[wn * (BN / 2) + j * 16][kk], BK + PAD);
#pragma unroll
            for (int i = 0; i < FR_M; i++)
#pragma unroll
                for (int j = 0; j < FR_N; j++)
                    wmma::mma_sync(cf[i][j], af[i], bf[j], cf[i][j]);
        }
        __syncthreads();
    }
#pragma unroll
    for (int i = 0; i < FR_M; i++)
#pragma unroll
        for (int j = 0; j < FR_N; j++)
            wmma::store_matrix_sync(&C[(long)(tm0 + wm * 32 + i * 16) * ldc + tn0 + wn * (BN / 2) + j * 16],
                                    cf[i][j], ldc, wmma::mem_row_major);
}

// ---------------- register-tiled SGEMM with packed f32x2 FMA ----------------
// EPI: 0 store, 1 accumulate, 3 relu(v+bias)
template<int BM, int BN, int BK, int TM, int TN, int EPI>
__global__ void gemm_k(const float* __restrict__ A, const float* __restrict__ B,
                       float* __restrict__ C,
                       int M, int N, int Kd, int lda, int ldb, int ldc,
                       long bsA, long bsB, long bsC,
                       const float* __restrict__ bias)
{
    constexpr int THREADS = (BM / TM) * (BN / TN);
    __shared__ __align__(16) float sA[BK][BM + 4];
    __shared__ __align__(16) float sB[BK][BN + 4];
    const int bz = blockIdx.z;
    A += (long)bz * bsA; B += (long)bz * bsB; C += (long)bz * bsC;
    const int tm0 = blockIdx.y * BM;
    const int tn0 = blockIdx.x * BN;
    const int tid = threadIdx.x;
    const int tcol = tid % (BN / TN);
    const int trow = tid / (BN / TN);

    unsigned long long acc2[TM][TN / 2];
#pragma unroll
    for (int i = 0; i < TM; i++)
#pragma unroll
        for (int j = 0; j < TN / 2; j++) acc2[i][j] = 0ull;

    for (int k0 = 0; k0 < Kd; k0 += BK) {
        constexpr int AITER = (BM * BK / 4 + THREADS - 1) / THREADS;
#pragma unroll
        for (int it = 0; it < AITER; it++) {
            int idx = tid + it * THREADS;
            if (idx < BM * BK / 4) {
                int m = idx >> 2, q = idx & 3;
                float4 v = *(const float4*)&A[(long)(tm0 + m) * lda + k0 + q * 4];
                sA[q * 4 + 0][m] = v.x;
                sA[q * 4 + 1][m] = v.y;
                sA[q * 4 + 2][m] = v.z;
                sA[q * 4 + 3][m] = v.w;
            }
        }
        constexpr int BITER = (BK * BN / 4 + THREADS - 1) / THREADS;
#pragma unroll
        for (int it = 0; it < BITER; it++) {
            int idx = tid + it * THREADS;
            if (idx < BK * BN / 4) {
                int kk = idx / (BN / 4), n4 = idx % (BN / 4);
                float4 v = *(const float4*)&B[(long)(k0 + kk) * ldb + tn0 + n4 * 4];
                *(float4*)&sB[kk][n4 * 4] = v;
            }
        }
        __syncthreads();
#pragma unroll
        for (int kk = 0; kk < BK; kk++) {
            float4 a0 = *(const float4*)&sA[kk][trow * TM];
            float4 a1 = *(const float4*)&sA[kk][trow * TM + 4];
            float av[8] = {a0.x, a0.y, a0.z, a0.w, a1.x, a1.y, a1.z, a1.w};
            unsigned long long b2[TN / 2];
            {
                float4 bx = *(const float4*)&sB[kk][tcol * TN];
                b2[0] = pack2(bx.x, bx.y);
                b2[1] = pack2(bx.z, bx.w);
                if (TN == 8) {
                    float4 by = *(const float4*)&sB[kk][tcol * TN + 4];
                    b2[2] = pack2(by.x, by.y);
                    b2[3] = pack2(by.z, by.w);
                }
            }
#pragma unroll
            for (int i = 0; i < TM; i++) {
                unsigned long long a2 = pack2(av[i], av[i]);
#pragma unroll
                for (int j = 0; j < TN / 2; j++) ffma2(acc2[i][j], a2, b2[j]);
            }
        }
        __syncthreads();
    }

#pragma unroll
    for (int i = 0; i < TM; i++) {
        int row = tm0 + trow * TM + i;
#pragma unroll
        for (int j2 = 0; j2 < TN / 2; j2++) {
            float v0, v1;
            unpack2(acc2[i][j2], v0, v1);
#pragma unroll
            for (int s = 0; s < 2; s++) {
                float v = s ? v1 : v0;
                int col = tn0 + tcol * TN + j2 * 2 + s;
                long off = (long)row * ldc + col;
                if (EPI == 1) v += C[off];
                if (EPI == 3) v = fmaxf(v + bias[col], 0.f);
                C[off] = v;
            }
        }
    }
}

// ---------------- fused attention kernel: one block per dst node ----------------
__global__ void attn_kernel(const float* __restrict__ ef, const float* __restrict__ dt,
                            const int* __restrict__ nidx,
                            const float* __restrict__ freq, const float* __restrict__ ph)
{
    const int n = blockIdx.x;
    const int tid = threadIdx.x;
    __shared__ __align__(16) float s_qh[512];
    __shared__ __align__(16) float s_wf[1536];
    __shared__ __align__(16) float s_te[32][132];
    __shared__ __align__(16) float s_e[32][68];
    __shared__ float s_dt[32];
    __shared__ int   s_idx[16];
    __shared__ float s_fr[128], s_ph[128];
    __shared__ float s_at[8][33];
    __shared__ float s_a2[8][17];
    __shared__ float s_ns[8][17];

    for (int i = tid; i < 512;  i += 256) s_qh[i] = g_proj[(long)n * 1536 + 1024 + i];
    for (int i = tid; i < 1536; i += 256) s_wf[i] = g_wfold[(long)n * 1536 + i];
    {
        const float4* ef4 = (const float4*)(ef + (long)n * 2048);
        for (int i = tid; i < 512; i += 256) {
            int l = i >> 4, c4 = i & 15;
            *(float4*)&s_e[l][c4 * 4] = ef4[i];
        }
    }
    if (tid < 128) { s_fr[tid] = freq[tid]; s_ph[tid] = ph[tid]; }
    if (tid < 32)  s_dt[tid] = dt[(long)n * 32 + tid];
    if (tid < 16)  s_idx[tid] = nidx[n * 16 + tid];
    __syncthreads();

    for (int i = tid; i < 4096; i += 256) {
        int l = i >> 7, d = i & 127;
        s_te[l][d] = cosf(s_dt[l] * s_fr[d] + s_ph[d]);
    }
    __syncthreads();

    const int h = tid >> 5, l = tid & 31;

    // node scores (16 distinct neighbors, coalesced)
    {
#pragma unroll
        for (int jb = 0; jb < 16; jb += 4) {
            int j = jb + (l >> 3);
            int d0 = (l & 7) * 8;
            const float4* p = (const float4*)(g_proj + (long)s_idx[j] * 1536 + h * 64 + d0);
            const float4* q = (const float4*)(s_qh + h * 64 + d0);
            float4 x0 = p[0], x1 = p[1];
            float4 q0 = q[0], q1 = q[1];
            float d = x0.x * q0.x + x0.y * q0.y + x0.z * q0.z + x0.w * q0.w
                    + x1.x * q1.x + x1.y * q1.y + x1.z * q1.z + x1.w * q1.w;
            d += __shfl_xor_sync(0xffffffffu, d, 1);
            d += __shfl_xor_sync(0xffffffffu, d, 2);
            d += __shfl_xor_sync(0xffffffffu, d, 4);
            if ((l & 7) == 0) s_ns[h][j] = d;
        }
        __syncwarp();
    }

    // scores + softmax
    {
        float sc = s_ns[h][l >> 1];
        const float4* ev = (const float4*)(&s_e[l][0]);
        const float4* we = (const float4*)(s_wf + h * 192);
#pragma unroll
        for (int j = 0; j < 16; j++) {
            float4 a = ev[j], b = we[j];
            sc += a.x * b.x + a.y * b.y + a.z * b.z + a.w * b.w;
        }
        const float4* tv = (const float4*)(&s_te[l][0]);
        const float4* wt = (const float4*)(s_wf + h * 192 + 64);
#pragma unroll
        for (int j = 0; j < 32; j++) {
            float4 a = tv[j], b = wt[j];
            sc += a.x * b.x + a.y * b.y + a.z * b.z + a.w * b.w;
        }
        sc *= 0.125f;
        float mx = sc;
        for (int o = 16; o; o >>= 1) mx = fmaxf(mx, __shfl_xor_sync(0xffffffffu, mx, o));
        float ex = expf(sc - mx);
        float sm = ex;
        for (int o = 16; o; o >>= 1) sm += __shfl_xor_sync(0xffffffffu, sm, o);
        float p = ex / sm;
        s_at[h][l] = p;
        float pp = p + __shfl_xor_sync(0xffffffffu, p, 1);
        if ((l & 1) == 0) s_a2[h][l >> 1] = pp;
    }
    __syncthreads();

    // ctx node part
    {
        int j = tid * 2;
        int hh = j >> 6;
        unsigned long long acc = 0ull;
#pragma unroll 4
        for (int r = 0; r < 16; r++) {
            float2 v = *(const float2*)&g_proj[(long)s_idx[r] * 1536 + 512 + j];
            float a = s_a2[hh][r];
            ffma2(acc, pack2(a, a), pack2(v.x, v.y));
        }
        float o0, o1;
        unpack2(acc, o0, o1);
        *(float2*)&g_ctx[(long)n * 512 + j] = make_float2(o0, o1);
    }
    // ebar / tbar
    for (int p = tid; p < 768; p += 256) {
        int hh = p / 96, c2 = (p % 96) * 2;
        unsigned long long acc = 0ull;
        if (c2 < 64) {
#pragma unroll
            for (int ll = 0; ll < 32; ll++) {
                float2 e = *(const float2*)&s_e[ll][c2];
                float a = s_at[hh][ll];
                ffma2(acc, pack2(a, a), pack2(e.x, e.y));
            }
        } else {
            int d = c2 - 64;
#pragma unroll
            for (int ll = 0; ll < 32; ll++) {
                float2 t2 = *(const float2*)&s_te[ll][d];
                float a = s_at[hh][ll];
                ffma2(acc, pack2(a, a), pack2(t2.x, t2.y));
            }
        }
        float o0, o1;
        unpack2(acc, o0, o1);
        *(float2*)&g_et[(long)n * 1536 + hh * 192 + c2] = make_float2(o0, o1);
    }
}

// ---------------- layernorm + concat (with fc epilogue fused) ----------------
__global__ void ln_kernel(const float* __restrict__ lng, const float* __restrict__ lnb,
                          const float* __restrict__ nf,  const float* __restrict__ fcb)
{
    const int n = blockIdx.x, tid = threadIdx.x; // 128 threads
    float xv[3];
    int cnt = 0;
    float s = 0.f, sq = 0.f;
    for (int i = tid; i < 320; i += 128) {
        float v = g_x[(long)n * 320 + i] + fcb[i];
        if (i < 128)       v += nf[(long)n * 128 + i];
        else if (i >= 192) v += g_cosph[i - 192];
        xv[cnt++] = v;
        s += v; sq += v * v;
    }
    __shared__ float rs[4], rq[4];
    for (int o = 16; o; o >>= 1) {
        s  += __shfl_xor_sync(0xffffffffu, s,  o);
        sq += __shfl_xor_sync(0xffffffffu, sq, o);
    }
    int wid = tid >> 5, lane = tid & 31;
    if (lane == 0) { rs[wid] = s; rq[wid] = sq; }
    __syncthreads();
    float ts = rs[0] + rs[1] + rs[2] + rs[3];
    float tq = rq[0] + rq[1] + rq[2] + rq[3];
    float mu = ts * (1.f / 320.f);
    float var = tq * (1.f / 320.f) - mu * mu;
    float inv = rsqrtf(var + 1e-5f);
    cnt = 0;
    for (int i = tid; i < 320; i += 128)
        g_hcat[(long)n * 448 + 128 + i] = lng[i] * (xv[cnt++] - mu) * inv + lnb[i];
    g_hcat[(long)n * 448 + tid] = nf[(long)n * 128 + tid];
}

// ---------------- launch ----------------
extern "C" void kernel_launch(void* const* d_in, const int* in_sizes, int n_in,
                              void* d_out, int out_size) {
    const float* nf   = (const float*)d_in[0];
    const float* ef   = (const float*)d_in[1];
    const float* dt   = (const float*)d_in[2];
    const int*   nidx = (const int*)  d_in[3];
    const float* freq = (const float*)d_in[4];
    const float* ph   = (const float*)d_in[5];
    const float* wqs  = (const float*)d_in[6];
    const float* wks  = (const float*)d_in[7];
    const float* wvs  = (const float*)d_in[8];
    const float* fcw  = (const float*)d_in[9];
    const float* fcb  = (const float*)d_in[10];
    const float* lng  = (const float*)d_in[11];
    const float* lnb  = (const float*)d_in[12];
    const float* nw   = (const float*)d_in[13];
    const float* nb   = (const float*)d_in[14];
    float* out = (float*)d_out;

    float *p_proj, *p_nodewT, *p_wvT, *p_wfold, *p_et, *p_ctx, *p_x;
    __nv_bfloat16 *p_A3, *p_B3, *p_ctx3, *p_fcw3;
    float *p_hcat;
    cudaGetSymbolAddress((void**)&p_proj,   g_proj);
    cudaGetSymbolAddress((void**)&p_nodewT, g_nodewT);
    cudaGetSymbolAddress((void**)&p_wvT,    g_wvT);
    cudaGetSymbolAddress((void**)&p_wfold,  g_wfold);
    cudaGetSymbolAddress((void**)&p_et,     g_et);
    cudaGetSymbolAddress((void**)&p_ctx,    g_ctx);
    cudaGetSymbolAddress((void**)&p_x,      g_x);
    cudaGetSymbolAddress((void**)&p_hcat,   g_hcat);
    cudaGetSymbolAddress((void**)&p_A3,     g_A3);
    cudaGetSymbolAddress((void**)&p_B3,     g_B3);
    cudaGetSymbolAddress((void**)&p_ctx3,   g_ctx3);
    cudaGetSymbolAddress((void**)&p_fcw3,   g_fcw3);

    // 1) pack weights / bias; bf16 splits of static operands
    prep_kernel<<<(516736 + 255) / 256, 256>>>(wks, wvs, wqs, fcw, nw, ph);
    convA_kernel<<<(N_SRC * 128 + 255) / 256, 256>>>(nf);
    convB_kernel<<<(128 * 1536 + 255) / 256, 256>>>();
    convFc_kernel<<<(320 * 512 + 255) / 256, 256>>>(fcw);

    // 2) node_k|node_v|qh projection via bf16-split tensor GEMM (K'=384)
    wmma_gemm<128,128><<<dim3(12, 128), 256>>>(p_A3, p_B3, p_proj, 384, 384, 384, 1536);
    qhbias_kernel<<<(N_DST * 512 + 255) / 256, 256>>>();

    // 3) fold q into K-weights, per head: (8192x192) = qh_h(8192x64) @ Wk_h(64x192)
    gemm_k<128,64,16,8,4,0><<<dim3(3,64,8), 256>>>(
        p_proj + 1024, wks + 128, p_wfold, N_DST, 192, 64, 1536, 320, 1536,
        64, (long)64 * 320, 192, nullptr);

    // 4) fused attention per dst
    attn_kernel<<<N_DST, 256>>>(ef, dt, nidx, freq, ph);

    // 5) V projection (accumulate): per head (8192x64) += et_h(8192x192) @ WvT_h(192x64)
    gemm_k<128,64,16,8,4,1><<<dim3(1,64,8), 256>>>(
        p_et, p_wvT, p_ctx, N_DST, 64, 192, 1536, 64, 512,
        192, (long)192 * 64, 64, nullptr);

    // 6) fc: x_base = ctx @ fc_w^T via bf16-split tensor GEMM (K'=1536); epilogue in ln
    convCtx_kernel<<<(N_DST * 512 + 255) / 256, 256>>>();
    wmma_gemm<128,64><<<dim3(5, 64), 256>>>(p_ctx3, p_fcw3, p_x, 1536, 1536, 1536, 320);

    // 7) layernorm + concat (+ fc bias/residuals fused)
    ln_kernel<<<N_DST, 128>>>(lng, lnb, nf, fcb);

    // 8) final: relu(hcat @ node_w^T + node_b)
    gemm_k<128,64,16,8,4,3><<<dim3(2,64,1), 256>>>(
        p_hcat, p_nodewT, out, N_DST, 128, 448, 448, 128, 128,
        0, 0, 0, nb);
}

// round 6
// speedup vs baseline: 1.6661x; 1.0490x over previous
#include <cuda_runtime.h>
#include <cuda_bf16.h>
#include <mma.h>
#include <math.h>

using namespace nvcuda;

#define N_SRC   16384
#define N_DST   8192

// ---------------- scratch (device globals; no allocations) ----------------
__device__ float g_proj[(long)N_SRC * 1536];   // [0:512) node_k | [512:1024) node_v | [1024:1536) qh
__device__ float g_biasq[512];
__device__ float g_cosph[128];
__device__ float g_wfold[(long)N_DST * 1536];
__device__ float g_ctx[(long)N_DST * 512];
__device__ float g_x[(long)N_DST * 320];
__device__ float g_xo[(long)N_DST * 128];
// bf16-split operands (A-style = [hi|lo|hi], B-style = [hi|hi|lo])
__device__ __nv_bfloat16 g_A3[(long)N_SRC * 384];      // nf split
__device__ __nv_bfloat16 g_B3[(long)1536 * 384];       // proj weights^T split
__device__ __nv_bfloat16 g_qh3[(long)N_DST * 1536];    // qh split, per head [hi64|lo64|hi64]
__device__ __nv_bfloat16 g_wk3[8 * 192 * 192];         // per-head K-fold weights split
__device__ __nv_bfloat16 g_et3[(long)N_DST * 4608];    // ebar/tbar split, per head [hi192|lo192|hi192]
__device__ __nv_bfloat16 g_wv3[8 * 64 * 576];          // per-head V weights split
__device__ __nv_bfloat16 g_ctx3[(long)N_DST * 1536];   // ctx split
__device__ __nv_bfloat16 g_fcw3[(long)320 * 1536];     // fc_w split
__device__ __nv_bfloat16 g_hcat3[(long)N_DST * 1344];  // hcat split
__device__ __nv_bfloat16 g_nodew3[(long)128 * 1344];   // node_w split

// ---------------- helpers ----------------
__device__ __forceinline__ unsigned long long pack2(float x, float y) {
    unsigned long long r;
    asm("mov.b64 %0, {%1, %2};" : "=l"(r) : "f"(x), "f"(y));
    return r;
}
__device__ __forceinline__ void unpack2(unsigned long long v, float& x, float& y) {
    asm("mov.b64 {%0, %1}, %2;" : "=f"(x), "=f"(y) : "l"(v));
}
__device__ __forceinline__ void ffma2(unsigned long long& d, unsigned long long a, unsigned long long b) {
    asm("fma.rn.f32x2 %0, %1, %2, %0;" : "+l"(d) : "l"(a), "l"(b));
}
__device__ __forceinline__ __nv_bfloat16 bsplit(float v, int is_lo) {
    __nv_bfloat16 h = __float2bfloat16(v);
    if (!is_lo) return h;
    return __float2bfloat16(v - __bfloat162float(h));
}

// ---------------- prep: all static weight splits + biasq + cosph ----------------
__global__ void prep_kernel(const float* __restrict__ wks, const float* __restrict__ wvs,
                            const float* __restrict__ wqs, const float* __restrict__ fcw,
                            const float* __restrict__ nw,  const float* __restrict__ ph)
{
    const int S0 = 589824;             // B3: 1536 x 384
    const int S1 = S0 + 294912;        // wk3: 8 x 192 x 192
    const int S2 = S1 + 294912;        // wv3: 8 x 64 x 576
    const int S3 = S2 + 491520;        // fcw3: 320 x 1536
    const int S4 = S3 + 172032;        // nodew3: 128 x 1344
    const int S5 = S4 + 512;           // biasq
    const int S6 = S5 + 128;           // cosph
    int t = blockIdx.x * blockDim.x + threadIdx.x;
    if (t < S0) {
        int r = t / 384, kp = t % 384;
        int k = kp & 127, seg = kp >> 7;
        float v;
        if (r < 512)       v = wks[r * 320 + k];
        else if (r < 1024) v = wvs[(r - 512) * 320 + k];
        else               v = wqs[(r - 1024) * 320 + k];
        g_B3[t] = bsplit(v, seg == 2);
    } else if (t < S1) {
        int i = t - S0;
        int h = i / 36864, rem = i % 36864;
        int c = rem / 192, kp = rem % 192;
        int d = kp & 63, seg = kp >> 6;
        float v = wks[(h * 64 + d) * 320 + 128 + c];
        g_wk3[i] = bsplit(v, seg == 2);
    } else if (t < S2) {
        int i = t - S1;
        int h = i / 36864, rem = i % 36864;
        int d = rem / 576, kp = rem % 576;
        int c = kp % 192, seg = kp / 192;
        float v = wvs[(h * 64 + d) * 320 + 128 + c];
        g_wv3[i] = bsplit(v, seg == 2);
    } else if (t < S3) {
        int i = t - S2;
        int c = i / 1536, kp = i % 1536;
        int j = kp & 511, seg = kp >> 9;
        float v = fcw[c * 512 + j];
        g_fcw3[i] = bsplit(v, seg == 2);
    } else if (t < S4) {
        int i = t - S3;
        int o = i / 1344, kp = i % 1344;
        int c = kp % 448, seg = kp / 448;
        float v = nw[o * 448 + c];
        g_nodew3[i] = bsplit(v, seg == 2);
    } else if (t < S5) {
        int j = t - S4;
        float acc = 0.f;
        for (int d = 0; d < 128; d++) acc += cosf(ph[d]) * wqs[j * 320 + 192 + d];
        g_biasq[j] = acc;
    } else if (t < S6) {
        g_cosph[t - S5] = cosf(ph[t - S5]);
    }
}

// ---------------- conversion kernels ----------------
__global__ void convA_kernel(const float* __restrict__ nf) {  // 16384 x 128 -> [hi|lo|hi]
    int i = blockIdx.x * 256 + threadIdx.x;
    if (i < N_SRC * 128) {
        int m = i >> 7, k = i & 127;
        float v = nf[i];
        __nv_bfloat16 hi = __float2bfloat16(v);
        __nv_bfloat16 lo = __float2bfloat16(v - __bfloat162float(hi));
        long b = (long)m * 384;
        g_A3[b + k] = hi;
        g_A3[b + 128 + k] = lo;
        g_A3[b + 256 + k] = hi;
    }
}
// add biasq to qh in place AND emit per-head split for gemm3
__global__ void qh3conv_kernel() {
    int i = blockIdx.x * 256 + threadIdx.x;
    if (i < N_DST * 512) {
        int n = i >> 9, j = i & 511;
        int h = j >> 6, d = j & 63;
        float v = g_proj[(long)n * 1536 + 1024 + j] + g_biasq[j];
        g_proj[(long)n * 1536 + 1024 + j] = v;
        __nv_bfloat16 hi = __float2bfloat16(v);
        __nv_bfloat16 lo = __float2bfloat16(v - __bfloat162float(hi));
        long b = (long)n * 1536 + h * 192;
        g_qh3[b + d] = hi;
        g_qh3[b + 64 + d] = lo;
        g_qh3[b + 128 + d] = hi;
    }
}
__global__ void convCtx_kernel() {  // g_ctx (8192 x 512) -> [hi|lo|hi]
    int i = blockIdx.x * 256 + threadIdx.x;
    if (i < N_DST * 512) {
        int n = i >> 9, j = i & 511;
        float v = g_ctx[i];
        __nv_bfloat16 hi = __float2bfloat16(v);
        __nv_bfloat16 lo = __float2bfloat16(v - __bfloat162float(hi));
        long b = (long)n * 1536;
        g_ctx3[b + j] = hi;
        g_ctx3[b + 512 + j] = lo;
        g_ctx3[b + 1024 + j] = hi;
    }
}
__global__ void relu_bias_kernel(const float* __restrict__ nb, float* __restrict__ out) {
    int i = blockIdx.x * 256 + threadIdx.x;
    if (i < N_DST * 128)
        out[i] = fmaxf(g_xo[i] + nb[i & 127], 0.f);
}

// ---------------- bf16 wmma GEMM: C =(or +=) A(MxK3) @ Bt(NxK3)^T, fp32 out ----------
// 256 threads = 8 warps (4 x 2). BM=128; BN in {64,128}. EPI: 0 store, 1 accumulate.
template<int BM, int BN, int EPI>
__global__ void wmma_gemm(const __nv_bfloat16* __restrict__ A,
                          const __nv_bfloat16* __restrict__ Bt,
                          float* __restrict__ C,
                          int K3, int lda, int ldb, int ldc,
                          long bsA, long bsB, long bsC)
{
    constexpr int BK = 32;
    constexpr int PAD = 8;
    constexpr int FR_M = BM / 64;
    constexpr int FR_N = BN / 32;
    __shared__ __align__(16) __nv_bfloat16 sA[BM][BK + PAD];
    __shared__ __align__(16) __nv_bfloat16 sB[BN][BK + PAD];
    const int bz = blockIdx.z;
    A += (long)bz * bsA; Bt += (long)bz * bsB; C += (long)bz * bsC;
    const int tid = threadIdx.x;
    const int wid = tid >> 5;
    const int wm = wid & 3;
    const int wn = wid >> 2;
    const int tm0 = blockIdx.y * BM;
    const int tn0 = blockIdx.x * BN;

    wmma::fragment<wmma::accumulator, 16, 16, 16, float> cf[FR_M][FR_N];
#pragma unroll
    for (int i = 0; i < FR_M; i++)
#pragma unroll
        for (int j = 0; j < FR_N; j++) {
            if (EPI == 1)
                wmma::load_matrix_sync(cf[i][j],
                    &C[(long)(tm0 + wm * 32 + i * 16) * ldc + tn0 + wn * (BN / 2) + j * 16],
                    ldc, wmma::mem_row_major);
            else
                wmma::fill_fragment(cf[i][j], 0.f);
        }

    for (int k0 = 0; k0 < K3; k0 += BK) {
        constexpr int A_LD = BM * (BK / 8) / 256;
#pragma unroll
        for (int it = 0; it < A_LD; it++) {
            int idx = tid + it * 256;
            int r = idx >> 2, c8 = idx & 3;
            *(int4*)&sA[r][c8 * 8] = *(const int4*)&A[(long)(tm0 + r) * lda + k0 + c8 * 8];
        }
        constexpr int B_LD = BN * (BK / 8) / 256;
#pragma unroll
        for (int it = 0; it < B_LD; it++) {
            int idx = tid + it * 256;
            int r = idx >> 2, c8 = idx & 3;
            *(int4*)&sB[r][c8 * 8] = *(const int4*)&Bt[(long)(tn0 + r) * ldb + k0 + c8 * 8];
        }
        __syncthreads();
#pragma unroll
        for (int kk = 0; kk < BK; kk += 16) {
            wmma::fragment<wmma::matrix_a, 16, 16, 16, __nv_bfloat16, wmma::row_major> af[FR_M];
            wmma::fragment<wmma::matrix_b, 16, 16, 16, __nv_bfloat16, wmma::col_major> bf[FR_N];
#pragma unroll
            for (int i = 0; i < FR_M; i++)
                wmma::load_matrix_sync(af[i], &sA[wm * 32 + i * 16][kk], BK + PAD);
#pragma unroll
            for (int j = 0; j < FR_N; j++)
                wmma::load_matrix_sync(bf[j], &sB[wn * (BN / 2) + j * 16][kk], BK + PAD);
#pragma unroll
            for (int i = 0; i < FR_M; i++)
#pragma unroll
                for (int j = 0; j < FR_N; j++)
                    wmma::mma_sync(cf[i][j], af[i], bf[j], cf[i][j]);
        }
        __syncthreads();
    }
#pragma unroll
    for (int i = 0; i < FR_M; i++)
#pragma unroll
        for (int j = 0; j < FR_N; j++)
            wmma::store_matrix_sync(&C[(long)(tm0 + wm * 32 + i * 16) * ldc + tn0 + wn * (BN / 2) + j * 16],
                                    cf[i][j], ldc, wmma::mem_row_major);
}

// ---------------- fused attention kernel: one block per dst node ----------------
__global__ void attn_kernel(const float* __restrict__ ef, const float* __restrict__ dt,
                            const int* __restrict__ nidx,
                            const float* __restrict__ freq, const float* __restrict__ ph)
{
    const int n = blockIdx.x;
    const int tid = threadIdx.x;
    __shared__ __align__(16) float s_qh[512];
    __shared__ __align__(16) float s_wf[1536];
    __shared__ __align__(16) float s_te[32][132];
    __shared__ __align__(16) float s_e[32][68];
    __shared__ float s_dt[32];
    __shared__ int   s_idx[16];
    __shared__ float s_fr[128], s_ph[128];
    __shared__ float s_at[8][33];
    __shared__ float s_a2[8][17];
    __shared__ float s_ns[8][17];

    for (int i = tid; i < 512;  i += 256) s_qh[i] = g_proj[(long)n * 1536 + 1024 + i];
    for (int i = tid; i < 1536; i += 256) s_wf[i] = g_wfold[(long)n * 1536 + i];
    {
        const float4* ef4 = (const float4*)(ef + (long)n * 2048);
        for (int i = tid; i < 512; i += 256) {
            int l = i >> 4, c4 = i & 15;
            *(float4*)&s_e[l][c4 * 4] = ef4[i];
        }
    }
    if (tid < 128) { s_fr[tid] = freq[tid]; s_ph[tid] = ph[tid]; }
    if (tid < 32)  s_dt[tid] = dt[(long)n * 32 + tid];
    if (tid < 16)  s_idx[tid] = nidx[n * 16 + tid];
    __syncthreads();

    for (int i = tid; i < 4096; i += 256) {
        int l = i >> 7, d = i & 127;
        s_te[l][d] = cosf(s_dt[l] * s_fr[d] + s_ph[d]);
    }
    __syncthreads();

    const int h = tid >> 5, l = tid & 31;

    // node scores (16 distinct neighbors, coalesced)
    {
#pragma unroll
        for (int jb = 0; jb < 16; jb += 4) {
            int j = jb + (l >> 3);
            int d0 = (l & 7) * 8;
            const float4* p = (const float4*)(g_proj + (long)s_idx[j] * 1536 + h * 64 + d0);
            const float4* q = (const float4*)(s_qh + h * 64 + d0);
            float4 x0 = p[0], x1 = p[1];
            float4 q0 = q[0], q1 = q[1];
            float d = x0.x * q0.x + x0.y * q0.y + x0.z * q0.z + x0.w * q0.w
                    + x1.x * q1.x + x1.y * q1.y + x1.z * q1.z + x1.w * q1.w;
            d += __shfl_xor_sync(0xffffffffu, d, 1);
            d += __shfl_xor_sync(0xffffffffu, d, 2);
            d += __shfl_xor_sync(0xffffffffu, d, 4);
            if ((l & 7) == 0) s_ns[h][j] = d;
        }
        __syncwarp();
    }

    // scores + softmax
    {
        float sc = s_ns[h][l >> 1];
        const float4* ev = (const float4*)(&s_e[l][0]);
        const float4* we = (const float4*)(s_wf + h * 192);
#pragma unroll
        for (int j = 0; j < 16; j++) {
            float4 a = ev[j], b = we[j];
            sc += a.x * b.x + a.y * b.y + a.z * b.z + a.w * b.w;
        }
        const float4* tv = (const float4*)(&s_te[l][0]);
        const float4* wt = (const float4*)(s_wf + h * 192 + 64);
#pragma unroll
        for (int j = 0; j < 32; j++) {
            float4 a = tv[j], b = wt[j];
            sc += a.x * b.x + a.y * b.y + a.z * b.z + a.w * b.w;
        }
        sc *= 0.125f;
        float mx = sc;
        for (int o = 16; o; o >>= 1) mx = fmaxf(mx, __shfl_xor_sync(0xffffffffu, mx, o));
        float ex = expf(sc - mx);
        float sm = ex;
        for (int o = 16; o; o >>= 1) sm += __shfl_xor_sync(0xffffffffu, sm, o);
        float p = ex / sm;
        s_at[h][l] = p;
        float pp = p + __shfl_xor_sync(0xffffffffu, p, 1);
        if ((l & 1) == 0) s_a2[h][l >> 1] = pp;
    }
    __syncthreads();

    // ctx node part (fp32, consumed as accumulator-init by wmma5)
    {
        int j = tid * 2;
        int hh = j >> 6;
        unsigned long long acc = 0ull;
#pragma unroll 4
        for (int r = 0; r < 16; r++) {
            float2 v = *(const float2*)&g_proj[(long)s_idx[r] * 1536 + 512 + j];
            float a = s_a2[hh][r];
            ffma2(acc, pack2(a, a), pack2(v.x, v.y));
        }
        float o0, o1;
        unpack2(acc, o0, o1);
        *(float2*)&g_ctx[(long)n * 512 + j] = make_float2(o0, o1);
    }
    // ebar / tbar -> write directly as bf16 [hi|lo|hi] per head (K'=576)
    for (int p = tid; p < 768; p += 256) {
        int hh = p / 96, c2 = (p % 96) * 2;
        unsigned long long acc = 0ull;
        if (c2 < 64) {
#pragma unroll
            for (int ll = 0; ll < 32; ll++) {
                float2 e = *(const float2*)&s_e[ll][c2];
                float a = s_at[hh][ll];
                ffma2(acc, pack2(a, a), pack2(e.x, e.y));
            }
        } else {
            int d = c2 - 64;
#pragma unroll
            for (int ll = 0; ll < 32; ll++) {
                float2 t2 = *(const float2*)&s_te[ll][d];
                float a = s_at[hh][ll];
                ffma2(acc, pack2(a, a), pack2(t2.x, t2.y));
            }
        }
        float o0, o1;
        unpack2(acc, o0, o1);
        __nv_bfloat16 h0 = __float2bfloat16(o0);
        __nv_bfloat16 h1 = __float2bfloat16(o1);
        __nv_bfloat16 l0 = __float2bfloat16(o0 - __bfloat162float(h0));
        __nv_bfloat16 l1 = __float2bfloat16(o1 - __bfloat162float(h1));
        long base = ((long)n * 8 + hh) * 576;
        __nv_bfloat162 hi2; hi2.x = h0; hi2.y = h1;
        __nv_bfloat162 lo2; lo2.x = l0; lo2.y = l1;
        *(__nv_bfloat162*)&g_et3[base + c2]       = hi2;
        *(__nv_bfloat162*)&g_et3[base + 192 + c2] = lo2;
        *(__nv_bfloat162*)&g_et3[base + 384 + c2] = hi2;
    }
}

// ---------------- layernorm + concat (fc epilogue fused; writes split hcat) ----------
__global__ void ln_kernel(const float* __restrict__ lng, const float* __restrict__ lnb,
                          const float* __restrict__ nf,  const float* __restrict__ fcb)
{
    const int n = blockIdx.x, tid = threadIdx.x; // 128 threads
    float xv[3];
    int cnt = 0;
    float s = 0.f, sq = 0.f;
    for (int i = tid; i < 320; i += 128) {
        float v = g_x[(long)n * 320 + i] + fcb[i];
        if (i < 128)       v += nf[(long)n * 128 + i];
        else if (i >= 192) v += g_cosph[i - 192];
        xv[cnt++] = v;
        s += v; sq += v * v;
    }
    __shared__ float rs[4], rq[4];
    for (int o = 16; o; o >>= 1) {
        s  += __shfl_xor_sync(0xffffffffu, s,  o);
        sq += __shfl_xor_sync(0xffffffffu, sq, o);
    }
    int wid = tid >> 5, lane = tid & 31;
    if (lane == 0) { rs[wid] = s; rq[wid] = sq; }
    __syncthreads();
    float ts = rs[0] + rs[1] + rs[2] + rs[3];
    float tq = rq[0] + rq[1] + rq[2] + rq[3];
    float mu = ts * (1.f / 320.f);
    float var = tq * (1.f / 320.f) - mu * mu;
    float inv = rsqrtf(var + 1e-5f);
    long b = (long)n * 1344;
    cnt = 0;
    for (int i = tid; i < 320; i += 128) {
        float w = lng[i] * (xv[cnt++] - mu) * inv + lnb[i];
        int c = 128 + i;
        __nv_bfloat16 hi = __float2bfloat16(w);
        __nv_bfloat16 lo = __float2bfloat16(w - __bfloat162float(hi));
        g_hcat3[b + c] = hi;
        g_hcat3[b + 448 + c] = lo;
        g_hcat3[b + 896 + c] = hi;
    }
    {
        float w = nf[(long)n * 128 + tid];
        __nv_bfloat16 hi = __float2bfloat16(w);
        __nv_bfloat16 lo = __float2bfloat16(w - __bfloat162float(hi));
        g_hcat3[b + tid] = hi;
        g_hcat3[b + 448 + tid] = lo;
        g_hcat3[b + 896 + tid] = hi;
    }
}

// ---------------- launch ----------------
extern "C" void kernel_launch(void* const* d_in, const int* in_sizes, int n_in,
                              void* d_out, int out_size) {
    const float* nf   = (const float*)d_in[0];
    const float* ef   = (const float*)d_in[1];
    const float* dt   = (const float*)d_in[2];
    const int*   nidx = (const int*)  d_in[3];
    const float* freq = (const float*)d_in[4];
    const float* ph   = (const float*)d_in[5];
    const float* wqs  = (const float*)d_in[6];
    const float* wks  = (const float*)d_in[7];
    const float* wvs  = (const float*)d_in[8];
    const float* fcw  = (const float*)d_in[9];
    const float* fcb  = (const float*)d_in[10];
    const float* lng  = (const float*)d_in[11];
    const float* lnb  = (const float*)d_in[12];
    const float* nw   = (const float*)d_in[13];
    const float* nb   = (const float*)d_in[14];
    float* out = (float*)d_out;

    float *p_proj, *p_wfold, *p_ctx, *p_x, *p_xo;
    __nv_bfloat16 *p_A3, *p_B3, *p_qh3, *p_wk3, *p_et3, *p_wv3, *p_ctx3, *p_fcw3, *p_hcat3, *p_nodew3;
    cudaGetSymbolAddress((void**)&p_proj,   g_proj);
    cudaGetSymbolAddress((void**)&p_wfold,  g_wfold);
    cudaGetSymbolAddress((void**)&p_ctx,    g_ctx);
    cudaGetSymbolAddress((void**)&p_x,      g_x);
    cudaGetSymbolAddress((void**)&p_xo,     g_xo);
    cudaGetSymbolAddress((void**)&p_A3,     g_A3);
    cudaGetSymbolAddress((void**)&p_B3,     g_B3);
    cudaGetSymbolAddress((void**)&p_qh3,    g_qh3);
    cudaGetSymbolAddress((void**)&p_wk3,    g_wk3);
    cudaGetSymbolAddress((void**)&p_et3,    g_et3);
    cudaGetSymbolAddress((void**)&p_wv3,    g_wv3);
    cudaGetSymbolAddress((void**)&p_ctx3,   g_ctx3);
    cudaGetSymbolAddress((void**)&p_fcw3,   g_fcw3);
    cudaGetSymbolAddress((void**)&p_hcat3,  g_hcat3);
    cudaGetSymbolAddress((void**)&p_nodew3, g_nodew3);

    // 1) weight splits + biasq + cosph; input split
    prep_kernel<<<(1843840 + 255) / 256, 256>>>(wks, wvs, wqs, fcw, nw, ph);
    convA_kernel<<<(N_SRC * 128 + 255) / 256, 256>>>(nf);

    // 2) node_k|node_v|qh projection (tensor): 16384x1536, K'=384
    wmma_gemm<128,128,0><<<dim3(12, 128), 256>>>(p_A3, p_B3, p_proj, 384, 384, 384, 1536, 0, 0, 0);
    qh3conv_kernel<<<(N_DST * 512 + 255) / 256, 256>>>();

    // 3) fold q into K-weights (tensor, batched per head): 8192x192, K'=192
    wmma_gemm<128,64,0><<<dim3(3, 64, 8), 256>>>(p_qh3, p_wk3, p_wfold, 192, 1536, 192, 1536,
                                                 192, (long)192 * 192, 192);

    // 4) fused attention per dst (writes g_ctx fp32 + g_et3 split)
    attn_kernel<<<N_DST, 256>>>(ef, dt, nidx, freq, ph);

    // 5) V projection (tensor, batched, accumulate onto ctx): 8192x64, K'=576
    wmma_gemm<128,64,1><<<dim3(1, 64, 8), 256>>>(p_et3, p_wv3, p_ctx, 576, 4608, 576, 512,
                                                 576, (long)64 * 576, 64);

    // 6) fc (tensor): 8192x320, K'=1536; epilogue fused in ln
    convCtx_kernel<<<(N_DST * 512 + 255) / 256, 256>>>();
    wmma_gemm<128,64,0><<<dim3(5, 64), 256>>>(p_ctx3, p_fcw3, p_x, 1536, 1536, 1536, 320, 0, 0, 0);

    // 7) layernorm + concat (writes split hcat)
    ln_kernel<<<N_DST, 128>>>(lng, lnb, nf, fcb);

    // 8) final (tensor): 8192x128, K'=1344; then relu+bias
    wmma_gemm<128,64,0><<<dim3(2, 64), 256>>>(p_hcat3, p_nodew3, p_xo, 1344, 1344, 1344, 128, 0, 0, 0);
    relu_bias_kernel<<<(N_DST * 128 + 255) / 256, 256>>>(nb, out);
}